// round 2
// baseline (speedup 1.0000x reference)
#include <cuda_runtime.h>
#include <cstdint>

#define NNODES 22
#define TB     500            // T (in = out feature dim)
#define BATCH  256
#define KDIM   1500           // 3 * TB
#define KP     1504           // padded K for BK=8 tiling
#define MROWS  (BATCH*NNODES) // 5632

#define BM 128
#define BN 128
#define BK 8

typedef unsigned long long u64;

// Scratch (device globals; no runtime allocation allowed)
__device__ float g_A [NNODES*NNODES];
__device__ float g_A2[NNODES*NNODES];
__device__ float g_Xp[(size_t)MROWS * KP];   // ~33.9 MB

// ---------------------------------------------------------------------------
// Kernel 1: A = softmax(adj, rows); A2 = A @ A
// ---------------------------------------------------------------------------
__global__ void prep_adj_kernel(const float* __restrict__ adj) {
    __shared__ float sA[NNODES*NNODES];
    int tid = threadIdx.x;
    if (tid < NNODES) {
        float e[NNODES];
        float mx = -1e30f;
        #pragma unroll
        for (int j = 0; j < NNODES; j++) mx = fmaxf(mx, adj[tid*NNODES + j]);
        float s = 0.f;
        #pragma unroll
        for (int j = 0; j < NNODES; j++) { e[j] = expf(adj[tid*NNODES + j] - mx); s += e[j]; }
        float inv = 1.f / s;
        #pragma unroll
        for (int j = 0; j < NNODES; j++) {
            float v = e[j] * inv;
            sA[tid*NNODES + j] = v;
            g_A[tid*NNODES + j] = v;
        }
    }
    __syncthreads();
    if (tid < NNODES*NNODES) {
        int n = tid / NNODES, m = tid - n*NNODES;
        float s = 0.f;
        #pragma unroll
        for (int k = 0; k < NNODES; k++) s = fmaf(sA[n*NNODES + k], sA[k*NNODES + m], s);
        g_A2[tid] = s;
    }
}

// ---------------------------------------------------------------------------
// Kernel 2: build X' = [x | A x | A^2 x], row = b*22+n, padded to KP cols.
// One block per batch; thread t handles one time index.
// ---------------------------------------------------------------------------
__global__ __launch_bounds__(512) void build_xp_kernel(const float* __restrict__ x) {
    __shared__ float sA[NNODES*NNODES], sA2[NNODES*NNODES];
    const int b = blockIdx.x;
    for (int i = threadIdx.x; i < NNODES*NNODES; i += blockDim.x) {
        sA[i]  = g_A[i];
        sA2[i] = g_A2[i];
    }
    __syncthreads();

    float* Xb = g_Xp + (size_t)b * NNODES * KP;

    // zero the K padding columns (1500..1503) of each of the 22 rows
    if (threadIdx.x < NNODES*4) {
        int n = threadIdx.x >> 2, j = threadIdx.x & 3;
        Xb[(size_t)n*KP + KDIM + j] = 0.f;
    }

    const int t = threadIdx.x;
    if (t < TB) {
        float xv[NNODES];
        const float* xb = x + (size_t)b * NNODES * TB;
        #pragma unroll
        for (int m = 0; m < NNODES; m++) xv[m] = xb[m*TB + t];
        #pragma unroll
        for (int n = 0; n < NNODES; n++) {
            float h1 = 0.f, h2 = 0.f;
            #pragma unroll
            for (int m = 0; m < NNODES; m++) {
                h1 = fmaf(sA [n*NNODES + m], xv[m], h1);
                h2 = fmaf(sA2[n*NNODES + m], xv[m], h2);
            }
            float* Xr = Xb + (size_t)n*KP;
            Xr[t]        = xv[n];
            Xr[TB + t]   = h1;
            Xr[2*TB + t] = h2;
        }
    }
}

// ---------------------------------------------------------------------------
// Packed fp32x2 helpers (Blackwell FFMA2 path — PTX only, ptxas won't emit it)
// ---------------------------------------------------------------------------
__device__ __forceinline__ u64 pack_dup(float v) {
    u64 r;
    asm("mov.b64 %0, {%1, %1};" : "=l"(r) : "f"(v));
    return r;
}
__device__ __forceinline__ void ffma2(u64& d, u64 a, u64 b) {
    asm("fma.rn.f32x2 %0, %1, %2, %0;" : "+l"(d) : "l"(a), "l"(b));
}

// ---------------------------------------------------------------------------
// Kernel 3: out = X' @ Wcat + b, replicated E times over the emb dim.
//   Wcat = W viewed as (1500, 500) row-major.
//   C tile 128x128, 256 threads, 8x8 micro-tile, f32x2 packed FMAs.
//   Cols per thread: two groups of 4 (tx*4 and 64+tx*4) -> conflict-free LDS.128.
// ---------------------------------------------------------------------------
__global__ void __launch_bounds__(256) gemm_out_kernel(
    const float* __restrict__ Wmat,
    const float* __restrict__ bias,
    float* __restrict__ out,
    int E)
{
    __shared__ float As[BK][BM];        // transposed A tile
    __shared__ float Bs[BK][BN + 4];    // padded

    const int tid = threadIdx.x;
    const int tx = tid & 15;            // 16 col-thread positions
    const int ty = tid >> 4;            // 16 row-thread positions
    const int row0 = blockIdx.y * BM;
    const int col0 = blockIdx.x * BN;

    // global load mapping
    const int a_r = tid >> 1;           // 0..127
    const int a_k = (tid & 1) << 2;     // 0 or 4
    const int b_k = tid >> 5;           // 0..7
    const int b_c = (tid & 31) << 2;    // 0..124

    const float* Aptr = g_Xp + (size_t)(row0 + a_r) * KP + a_k;

    u64 acc[8][2][2];
    #pragma unroll
    for (int i = 0; i < 8; i++)
        #pragma unroll
        for (int g = 0; g < 2; g++) { acc[i][g][0] = 0ull; acc[i][g][1] = 0ull; }

    for (int k0 = 0; k0 < KP; k0 += BK) {
        float4 av = *reinterpret_cast<const float4*>(Aptr + k0);
        float4 bv = make_float4(0.f, 0.f, 0.f, 0.f);
        const int kg = k0 + b_k;
        const int cg = col0 + b_c;
        if (kg < KDIM && cg < TB)
            bv = *reinterpret_cast<const float4*>(Wmat + (size_t)kg * TB + cg);

        As[a_k+0][a_r] = av.x;
        As[a_k+1][a_r] = av.y;
        As[a_k+2][a_r] = av.z;
        As[a_k+3][a_r] = av.w;
        *reinterpret_cast<float4*>(&Bs[b_k][b_c]) = bv;
        __syncthreads();

        #pragma unroll
        for (int kk = 0; kk < BK; kk++) {
            float4 a0 = *reinterpret_cast<const float4*>(&As[kk][ty*8]);
            float4 a1 = *reinterpret_cast<const float4*>(&As[kk][ty*8 + 4]);
            u64 ad[8];
            ad[0] = pack_dup(a0.x); ad[1] = pack_dup(a0.y);
            ad[2] = pack_dup(a0.z); ad[3] = pack_dup(a0.w);
            ad[4] = pack_dup(a1.x); ad[5] = pack_dup(a1.y);
            ad[6] = pack_dup(a1.z); ad[7] = pack_dup(a1.w);
            #pragma unroll
            for (int g = 0; g < 2; g++) {
                const u64* bp = reinterpret_cast<const u64*>(&Bs[kk][g*64 + tx*4]);
                u64 b0 = bp[0], b1 = bp[1];
                #pragma unroll
                for (int i = 0; i < 8; i++) {
                    ffma2(acc[i][g][0], ad[i], b0);
                    ffma2(acc[i][g][1], ad[i], b1);
                }
            }
        }
        __syncthreads();
    }

    // ---- epilogue: bias + replicate E copies -----------------------------
    float bias2[2][4];
    #pragma unroll
    for (int g = 0; g < 2; g++)
        #pragma unroll
        for (int j = 0; j < 4; j++) {
            int c = col0 + g*64 + tx*4 + j;
            bias2[g][j] = (c < TB) ? bias[c] : 0.f;
        }

    const size_t eStride = (size_t)NNODES * TB;   // 11000
    const int rbase = row0 + ty*8;
    int bb0 = rbase / NNODES;
    int nn0 = rbase - bb0 * NNODES;
    #pragma unroll
    for (int i = 0; i < 8; i++) {
        int bb = bb0, nn = nn0 + i;
        if (nn >= NNODES) { nn -= NNODES; bb += 1; }
        size_t base = (size_t)bb * E * eStride + (size_t)nn * TB;
        #pragma unroll
        for (int g = 0; g < 2; g++) {
            int c = col0 + g*64 + tx*4;
            if (c >= TB) continue;
            float2 p0 = *reinterpret_cast<float2*>(&acc[i][g][0]);
            float2 p1 = *reinterpret_cast<float2*>(&acc[i][g][1]);
            float4 v = make_float4(p0.x + bias2[g][0], p0.y + bias2[g][1],
                                   p1.x + bias2[g][2], p1.y + bias2[g][3]);
            float* p = out + base + c;
            for (int e = 0; e < E; e++) {
                *reinterpret_cast<float4*>(p) = v;
                p += eStride;
            }
        }
    }
}

// ---------------------------------------------------------------------------
// Launch. Inputs (metadata order): x, adj, W, b, emb_size.
// ---------------------------------------------------------------------------
extern "C" void kernel_launch(void* const* d_in, const int* in_sizes, int n_in,
                              void* d_out, int out_size) {
    const float* x    = (const float*)d_in[0];   // (256, 22, 500)
    const float* adj  = (const float*)d_in[1];   // (22, 22)
    const float* Wmat = (const float*)d_in[2];   // (3, 500, 500) == (1500, 500)
    const float* bias = (const float*)d_in[3];   // (500,)
    float* out = (float*)d_out;

    // E derived from output size (avoids emb_size dtype ambiguity)
    const int E = out_size / (BATCH * NNODES * TB);

    prep_adj_kernel<<<1, 512>>>(adj);
    build_xp_kernel<<<BATCH, 512>>>(x);

    dim3 grid((TB + BN - 1) / BN, MROWS / BM);   // (4, 44)
    gemm_out_kernel<<<grid, 256>>>(Wmat, bias, out, E);
}

// round 6
// speedup vs baseline: 1.8850x; 1.8850x over previous
#include <cuda_runtime.h>
#include <cuda_bf16.h>
#include <cstdint>

#define NNODES 22
#define TB     500
#define BATCH  256
#define MROWS  (BATCH*NNODES)   // 5632
#define HOPP   512              // padded per-hop K stride
#define KBLK   1536             // per split-block K (3 hops x 512)
#define KTOT   4608             // [Xh | Xl | Xh] K
#define NTOT   512              // padded N
#define KT     144              // K-blocks of 32

#define BM 256
#define BN 128
#define BKK 32
#define THREADS 512

typedef unsigned long long u64;

// ---------------- device scratch ------------------------------------------
__device__ float         g_A [NNODES*NNODES];
__device__ float         g_A2[NNODES*NNODES];
__device__ __nv_bfloat16 g_Xbf[(size_t)MROWS*KTOT];   // 51.9 MB
__device__ __nv_bfloat16 g_Wbf[(size_t)NTOT*KTOT];    // 4.7 MB
__device__ float         g_C  [(size_t)MROWS*NTOT];   // 11.5 MB

// ---------------------------------------------------------------------------
// Kernel 1: A = softmax(adj), A2 = A@A
// ---------------------------------------------------------------------------
__global__ void prep_adj_kernel(const float* __restrict__ adj) {
    __shared__ float sA[NNODES*NNODES];
    int tid = threadIdx.x;
    if (tid < NNODES) {
        float e[NNODES], mx = -1e30f;
        #pragma unroll
        for (int j = 0; j < NNODES; j++) mx = fmaxf(mx, adj[tid*NNODES + j]);
        float s = 0.f;
        #pragma unroll
        for (int j = 0; j < NNODES; j++) { e[j] = expf(adj[tid*NNODES + j] - mx); s += e[j]; }
        float inv = 1.f / s;
        #pragma unroll
        for (int j = 0; j < NNODES; j++) {
            float v = e[j] * inv;
            sA[tid*NNODES + j] = v;
            g_A[tid*NNODES + j] = v;
        }
    }
    __syncthreads();
    if (tid < NNODES*NNODES) {
        int n = tid / NNODES, m = tid - n*NNODES;
        float s = 0.f;
        #pragma unroll
        for (int k = 0; k < NNODES; k++) s = fmaf(sA[n*NNODES + k], sA[k*NNODES + m], s);
        g_A2[tid] = s;
    }
}

// ---------------------------------------------------------------------------
// Kernel 2: g_Xbf = bf16 split of [x | Ax | A2x], K-blocks [hi | lo | hi]
// ---------------------------------------------------------------------------
__global__ __launch_bounds__(512) void build_xbf_kernel(const float* __restrict__ x) {
    __shared__ float sA[NNODES*NNODES], sA2[NNODES*NNODES];
    const int b = blockIdx.x;
    for (int i = threadIdx.x; i < NNODES*NNODES; i += blockDim.x) {
        sA[i] = g_A[i]; sA2[i] = g_A2[i];
    }
    __syncthreads();

    const int t = threadIdx.x;
    __nv_bfloat16* Xb = g_Xbf + (size_t)b * NNODES * KTOT;

    if (t < TB) {
        float xv[NNODES];
        const float* xb = x + (size_t)b * NNODES * TB;
        #pragma unroll
        for (int m = 0; m < NNODES; m++) xv[m] = xb[m*TB + t];
        #pragma unroll
        for (int n = 0; n < NNODES; n++) {
            float h1 = 0.f, h2 = 0.f;
            #pragma unroll
            for (int m = 0; m < NNODES; m++) {
                h1 = fmaf(sA [n*NNODES + m], xv[m], h1);
                h2 = fmaf(sA2[n*NNODES + m], xv[m], h2);
            }
            float v0 = xv[n];
            __nv_bfloat16 hi0 = __float2bfloat16(v0);
            __nv_bfloat16 hi1 = __float2bfloat16(h1);
            __nv_bfloat16 hi2 = __float2bfloat16(h2);
            __nv_bfloat16 lo0 = __float2bfloat16(v0 - __bfloat162float(hi0));
            __nv_bfloat16 lo1 = __float2bfloat16(h1 - __bfloat162float(hi1));
            __nv_bfloat16 lo2 = __float2bfloat16(h2 - __bfloat162float(hi2));
            __nv_bfloat16* R = Xb + (size_t)n * KTOT;
            R[t] = hi0;  R[HOPP + t] = hi1;  R[2*HOPP + t] = hi2;
            R[KBLK + t] = lo0;  R[KBLK + HOPP + t] = lo1;  R[KBLK + 2*HOPP + t] = lo2;
            R[2*KBLK + t] = hi0;  R[2*KBLK + HOPP + t] = hi1;  R[2*KBLK + 2*HOPP + t] = hi2;
        }
    } else {  // t in [500, 512): zero padding columns
        __nv_bfloat16 z = __float2bfloat16(0.f);
        #pragma unroll
        for (int n = 0; n < NNODES; n++) {
            __nv_bfloat16* R = Xb + (size_t)n * KTOT;
            #pragma unroll
            for (int blk = 0; blk < 3; blk++)
                #pragma unroll
                for (int hop = 0; hop < 3; hop++)
                    R[blk*KBLK + hop*HOPP + t] = z;
        }
    }
}

// ---------------------------------------------------------------------------
// Kernel 3: g_Wbf[n][k] (K-major B), blocks [Wh | Wh | Wl]
// ---------------------------------------------------------------------------
__global__ __launch_bounds__(512) void build_wbf_kernel(const float* __restrict__ W) {
    const int n = blockIdx.x;   // 0..511
    for (int k = threadIdx.x; k < KTOT; k += 512) {
        int blk = k / KBLK;
        int kk  = k - blk*KBLK;
        int hop = kk >> 9;
        int tp  = kk & 511;
        float v = 0.f;
        if (tp < TB && n < TB) v = W[((size_t)hop*TB + tp)*TB + n];
        __nv_bfloat16 hv = __float2bfloat16(v);
        __nv_bfloat16 ov = hv;
        if (blk == 2) ov = __float2bfloat16(v - __bfloat162float(hv));
        g_Wbf[(size_t)n*KTOT + k] = ov;
    }
}

// ---------------------------------------------------------------------------
// Kernel 4: mma.sync bf16 GEMM: g_C = Xbf * Wbf^T (both K-major)
//   block 256x128x32, 512 thr, warp 64x32, double-buffered cp.async
// ---------------------------------------------------------------------------

// Swizzle for 64B rows packed as 128B atoms of 2 rows; conflict-free for
// ldmatrix 8-row groups and cp.async 16B stores.
__device__ __forceinline__ uint32_t sw_off(int r, int c) {
    int chunk8 = ((r & 1) << 2) | c;
    return (uint32_t)((r >> 1) * 128 + ((chunk8 ^ ((r >> 1) & 7)) << 4));
}

__device__ __forceinline__ uint32_t smem_u32(const void* p) {
    uint32_t a;
    asm("{ .reg .u64 t; cvta.to.shared.u64 t, %1; cvt.u32.u64 %0, t; }" : "=r"(a) : "l"(p));
    return a;
}
__device__ __forceinline__ void cp16(uint32_t dst, const void* src) {
    asm volatile("cp.async.cg.shared.global [%0], [%1], 16;" :: "r"(dst), "l"(src));
}
__device__ __forceinline__ void ldm_x4(uint32_t* q, uint32_t addr) {
    asm volatile("ldmatrix.sync.aligned.m8n8.x4.shared.b16 {%0,%1,%2,%3}, [%4];"
                 : "=r"(q[0]), "=r"(q[1]), "=r"(q[2]), "=r"(q[3]) : "r"(addr));
}
__device__ __forceinline__ void mma_bf16(float* c, const uint32_t* a, uint32_t b0, uint32_t b1) {
    asm volatile("mma.sync.aligned.m16n8k16.row.col.f32.bf16.bf16.f32 "
                 "{%0,%1,%2,%3}, {%4,%5,%6,%7}, {%8,%9}, {%0,%1,%2,%3};"
                 : "+f"(c[0]), "+f"(c[1]), "+f"(c[2]), "+f"(c[3])
                 : "r"(a[0]), "r"(a[1]), "r"(a[2]), "r"(a[3]), "r"(b0), "r"(b1));
}

#define A_STAGE 16384   // 256 rows * 64B
#define B_STAGE 8192    // 128 rows * 64B

__global__ void __launch_bounds__(THREADS, 1) gemm_mma_kernel() {
    __shared__ __align__(128) unsigned char smem[2*A_STAGE + 2*B_STAGE];  // 48 KB

    const int tid  = threadIdx.x;
    const int lane = tid & 31;
    const int wid  = tid >> 5;
    const int wm   = wid & 3;        // 4 warps over M (64 rows each)
    const int wn   = wid >> 2;       // 4 warps over N (32 cols each)
    const int row0 = blockIdx.y * BM;
    const int n0   = blockIdx.x * BN;

    const uint32_t sA0 = smem_u32(smem);
    const uint32_t sB0 = sA0 + 2*A_STAGE;

    const char* gA = reinterpret_cast<const char*>(g_Xbf);
    const char* gB = reinterpret_cast<const char*>(g_Wbf);

    const int a_r0 = tid >> 2, a_c = tid & 3;
    const int b_r  = tid >> 2, b_c = tid & 3;
    const uint32_t aoff0 = sw_off(a_r0,       a_c);
    const uint32_t aoff1 = sw_off(a_r0 + 128, a_c);
    const uint32_t boff  = sw_off(b_r,        b_c);
    const char* aptr0 = gA + ((size_t)(row0 + a_r0      ) * KTOT + a_c*8) * 2;
    const char* aptr1 = gA + ((size_t)(row0 + a_r0 + 128) * KTOT + a_c*8) * 2;
    const char* bptr  = gB + ((size_t)(n0   + b_r       ) * KTOT + b_c*8) * 2;

    float acc[4][4][4];
    #pragma unroll
    for (int i = 0; i < 4; i++)
        #pragma unroll
        for (int j = 0; j < 4; j++)
            #pragma unroll
            for (int q = 0; q < 4; q++) acc[i][j][q] = 0.f;

    // prologue: stage 0 loads k-block 0
    cp16(sA0 + aoff0, aptr0);
    cp16(sA0 + aoff1, aptr1);
    cp16(sB0 + boff,  bptr);
    asm volatile("cp.async.commit_group;" ::: "memory");

    const int lr = lane & 15;          // row within 16-row group
    const int lc = lane >> 4;          // k half chunk

    for (int kb = 0; kb < KT; kb++) {
        __syncthreads();   // compute(kb-1) done before overwriting its buffer
        const int nkb = kb + 1;
        if (nkb < KT) {
            const uint32_t sa = sA0 + (nkb & 1) * A_STAGE;
            const uint32_t sb = sB0 + (nkb & 1) * B_STAGE;
            const size_t kbyte = (size_t)nkb * BKK * 2;
            cp16(sa + aoff0, aptr0 + kbyte);
            cp16(sa + aoff1, aptr1 + kbyte);
            cp16(sb + boff,  bptr  + kbyte);
        }
        asm volatile("cp.async.commit_group;" ::: "memory");
        asm volatile("cp.async.wait_group 1;" ::: "memory");
        __syncthreads();

        const uint32_t sa = sA0 + (kb & 1) * A_STAGE;
        const uint32_t sb = sB0 + (kb & 1) * B_STAGE;

        #pragma unroll
        for (int ks = 0; ks < 2; ks++) {
            const int c = ks*2 + lc;
            uint32_t af[4][4];
            #pragma unroll
            for (int mi = 0; mi < 4; mi++)
                ldm_x4(af[mi], sa + sw_off(wm*64 + mi*16 + lr, c));
            uint32_t bq0[4], bq1[4];
            ldm_x4(bq0, sb + sw_off(wn*32 +  0 + lr, c));
            ldm_x4(bq1, sb + sw_off(wn*32 + 16 + lr, c));
            #pragma unroll
            for (int mi = 0; mi < 4; mi++) {
                mma_bf16(acc[mi][0], af[mi], bq0[0], bq0[2]);
                mma_bf16(acc[mi][1], af[mi], bq0[1], bq0[3]);
                mma_bf16(acc[mi][2], af[mi], bq1[0], bq1[2]);
                mma_bf16(acc[mi][3], af[mi], bq1[1], bq1[3]);
            }
        }
    }

    // ---- epilogue: fragments -> g_C ----
    const int crow = lane >> 2;
    const int ccol = (lane & 3) * 2;
    #pragma unroll
    for (int mi = 0; mi < 4; mi++) {
        const int r = row0 + wm*64 + mi*16 + crow;
        #pragma unroll
        for (int ni = 0; ni < 4; ni++) {
            const int cbase = n0 + wn*32 + ni*8 + ccol;
            *reinterpret_cast<float2*>(&g_C[(size_t)r      *NTOT + cbase]) =
                make_float2(acc[mi][ni][0], acc[mi][ni][1]);
            *reinterpret_cast<float2*>(&g_C[(size_t)(r + 8)*NTOT + cbase]) =
                make_float2(acc[mi][ni][2], acc[mi][ni][3]);
        }
    }
}

// ---------------------------------------------------------------------------
// Kernel 5: out[b, e, n, :] = g_C[b*22+n, 0:500] + bias, for all e
//   2 rows per block, 256 threads (125 float4 per row).
// ---------------------------------------------------------------------------
__global__ __launch_bounds__(256) void replicate_kernel(
    const float* __restrict__ bias, float* __restrict__ out, int E)
{
    const int half = threadIdx.x >> 7;            // 0 or 1
    const int t4   = threadIdx.x & 127;           // float4 index in row
    const int m = blockIdx.x * 2 + half;          // 0..5631
    if (t4 >= TB/4) return;
    const int bb = m / NNODES, nn = m - bb*NNODES;
    float4 v  = *reinterpret_cast<const float4*>(&g_C[(size_t)m*NTOT + t4*4]);
    float4 bv = *reinterpret_cast<const float4*>(&bias[t4*4]);
    v.x += bv.x; v.y += bv.y; v.z += bv.z; v.w += bv.w;
    float* p = out + (size_t)bb * E * (NNODES*TB) + (size_t)nn * TB + t4*4;
    #pragma unroll 4
    for (int e = 0; e < E; e++) {
        *reinterpret_cast<float4*>(p) = v;
        p += NNODES*TB;
    }
}

// ---------------------------------------------------------------------------
// Launch. Inputs: x, adj, W, b, emb_size.
// ---------------------------------------------------------------------------
extern "C" void kernel_launch(void* const* d_in, const int* in_sizes, int n_in,
                              void* d_out, int out_size) {
    const float* x    = (const float*)d_in[0];
    const float* adj  = (const float*)d_in[1];
    const float* Wmat = (const float*)d_in[2];
    const float* bias = (const float*)d_in[3];
    float* out = (float*)d_out;
    const int E = out_size / (BATCH * NNODES * TB);

    prep_adj_kernel<<<1, 512>>>(adj);
    build_xbf_kernel<<<BATCH, 512>>>(x);
    build_wbf_kernel<<<NTOT, 512>>>(Wmat);

    dim3 grid(NTOT / BN, MROWS / BM);   // (4, 22) = 88 blocks
    gemm_mma_kernel<<<grid, THREADS>>>();

    replicate_kernel<<<MROWS/2, 256>>>(bias, out, E);
}